// round 7
// baseline (speedup 1.0000x reference)
#include <cuda_runtime.h>
#include <cuda_bf16.h>
#include <stdint.h>

#define Dd 128
#define Ll 200
#define Bb 4096
#define NITEMS 100000

// Scratch (static device globals: allocation-free per harness rules)
__device__ __nv_bfloat16 g_KWh[(NITEMS + 1) * Dd];  // item_emb @ Wk (bf16)
__device__ __nv_bfloat16 g_Ih[(NITEMS + 1) * Dd];   // item_emb in bf16 (GEMM input only)
__device__ __nv_bfloat16 g_Uh[Bb * Dd];             // gathered user rows (bf16)
__device__ float g_Q[Bb * Dd];                      // Q = u@Wq + b_att (fp32)
__device__ float g_klp[Bb];
__device__ int   g_cnt[Bb];

// ---------------------------------------------------------------- utilities

__device__ __forceinline__ uint32_t rotl32(uint32_t x, int d) {
    return (x << d) | (x >> (32 - d));
}

// Exact JAX threefry2x32 (20 rounds)
__device__ __forceinline__ void threefry2x32(uint32_t k0, uint32_t k1,
                                             uint32_t c0, uint32_t c1,
                                             uint32_t& o0, uint32_t& o1) {
    uint32_t ks2 = k0 ^ k1 ^ 0x1BD11BDAu;
    uint32_t x0 = c0 + k0, x1 = c1 + k1;
#define TF_R(r) { x0 += x1; x1 = rotl32(x1, r); x1 ^= x0; }
    TF_R(13) TF_R(15) TF_R(26) TF_R(6)  x0 += k1;  x1 += ks2 + 1u;
    TF_R(17) TF_R(29) TF_R(16) TF_R(24) x0 += ks2; x1 += k0 + 2u;
    TF_R(13) TF_R(15) TF_R(26) TF_R(6)  x0 += k0;  x1 += k1 + 3u;
    TF_R(17) TF_R(29) TF_R(16) TF_R(24) x0 += k1;  x1 += ks2 + 4u;
    TF_R(13) TF_R(15) TF_R(26) TF_R(6)  x0 += ks2; x1 += k0 + 5u;
#undef TF_R
    o0 = x0; o1 = x1;
}

// jax.random.normal under jax_threefry_partitionable=True:
//   counter = 64-bit flat index -> (c0 = 0, c1 = idx); 32-bit draw = o0 ^ o1
__device__ __forceinline__ float jax_normal(uint32_t k1, uint32_t idx) {
    uint32_t o0, o1;
    threefry2x32(0u, k1, 0u, idx, o0, o1);
    uint32_t bits = o0 ^ o1;
    float f = __uint_as_float((bits >> 9) | 0x3F800000u) - 1.0f;  // [0,1)
    const float LO = -0.99999994f;                                // nextafter(-1,0)
    float u = fmaf(f, 2.0f, LO);
    u = fmaxf(u, LO);
    return 1.41421356f * erfinvf(u);
}

__device__ __forceinline__ float fast_tanh(float x) {
    float y;
    asm("tanh.approx.f32 %0, %1;" : "=f"(y) : "f"(x));
    return y;
}

__device__ __forceinline__ float breduce_sum(float v, volatile float* red) {
    int tid = threadIdx.x, lane = tid & 31, wrp = tid >> 5;
#pragma unroll
    for (int o = 16; o; o >>= 1) v += __shfl_down_sync(0xffffffffu, v, o);
    if (lane == 0) red[wrp] = v;
    __syncthreads();
    float r = (red[0] + red[1]) + (red[2] + red[3]);
    __syncthreads();
    return r;
}

__device__ __forceinline__ float breduce_max(float v, volatile float* red) {
    int tid = threadIdx.x, lane = tid & 31, wrp = tid >> 5;
#pragma unroll
    for (int o = 16; o; o >>= 1) v = fmaxf(v, __shfl_down_sync(0xffffffffu, v, o));
    if (lane == 0) red[wrp] = v;
    __syncthreads();
    float r = fmaxf(fmaxf(red[0], red[1]), fmaxf(red[2], red[3]));
    __syncthreads();
    return r;
}

// ------------------------------------------- Kernel 0a: item_emb -> bf16 table
__global__ __launch_bounds__(256) void conv_item_kernel(const float* __restrict__ item_emb) {
    const int total = (NITEMS + 1) * (Dd / 4);          // float4 count
    for (int i = blockIdx.x * 256 + threadIdx.x; i < total; i += gridDim.x * 256) {
        float4 v = ((const float4*)item_emb)[i];
        __nv_bfloat162 lo = __floats2bfloat162_rn(v.x, v.y);
        __nv_bfloat162 hi = __floats2bfloat162_rn(v.z, v.w);
        uint2 p;
        p.x = *(uint32_t*)&lo;
        p.y = *(uint32_t*)&hi;
        ((uint2*)g_Ih)[i] = p;
    }
}

// ------------------------------------------- Kernel 0b: gather user rows -> bf16
__global__ __launch_bounds__(256) void conv_user_kernel(const float* __restrict__ user_emb,
                                                        const int* __restrict__ user_idx) {
    const int total = Bb * (Dd / 4);
    for (int i = blockIdx.x * 256 + threadIdx.x; i < total; i += gridDim.x * 256) {
        int u = i >> 5, c = i & 31;
        int src = user_idx[u];
        float4 v = ((const float4*)(user_emb + (size_t)src * Dd))[c];
        __nv_bfloat162 lo = __floats2bfloat162_rn(v.x, v.y);
        __nv_bfloat162 hi = __floats2bfloat162_rn(v.z, v.w);
        uint2 p;
        p.x = *(uint32_t*)&lo;
        p.y = *(uint32_t*)&hi;
        ((uint2*)g_Uh)[i] = p;
    }
}

// =================================================================
// bf16 m16n8k16 MMA; smem tiles: uint32 k-pairs, row stride PADU uint32
// =================================================================
#define PADU 68

// ------------------------------------------- Kernel A: KW = item_emb @ Wk (bf16 MMA)
// Persistent 148 blocks x 256 thr (8 warps), 2 blocks/SM.
// 128-row A tiles double-buffered via cp.async from g_Ih.
#define KW_GRID 148
#define KW_TILES ((NITEMS + 1 + 127) / 128)   // 782

__global__ __launch_bounds__(256, 2) void kw_kernel(const float* __restrict__ Wk) {
    extern __shared__ uint32_t smem_u[];
    uint32_t* sW  = smem_u;                    // [128 n][68]
    uint32_t* sA0 = smem_u + 128 * PADU;
    uint32_t* sA1 = sA0 + 128 * PADU;

    const int tid  = threadIdx.x;
    const int lane = tid & 31;
    const int wid  = tid >> 5;
    const int gid  = lane >> 2;      // 0..7
    const int tig  = lane & 3;       // 0..3
    const int stripe = (wid & 3) * 32;
    const int colh   = (wid >> 2) * 64;

    // sW[n][p] = {bf16(Wk[2p][n]), bf16(Wk[2p+1][n])}
    for (int i = tid; i < 128 * 64; i += 256) {
        int n = i >> 6, p = i & 63;
        __nv_bfloat162 h = __floats2bfloat162_rn(Wk[(2 * p) * Dd + n],
                                                 Wk[(2 * p + 1) * Dd + n]);
        sW[n * PADU + p] = *(uint32_t*)&h;
    }

    uint32_t* bufs[2] = { sA0, sA1 };
    int cur = 0;
    int t = blockIdx.x;

    // async tile loader: 128 rows x 16 16B-chunks (bf16 rows = 256B)
#define LOAD_TILE(dst, tt) do {                                               \
        const int row0_ = (tt) * 128;                                         \
        for (int i = tid; i < 128 * 16; i += 256) {                           \
            int r_ = i >> 4, c_ = i & 15;                                     \
            int sr_ = row0_ + r_; if (sr_ > NITEMS) sr_ = NITEMS;             \
            const char* src_ = (const char*)g_Ih + (size_t)sr_ * 256 + c_ * 16;\
            uint32_t d_ = (uint32_t)__cvta_generic_to_shared(                 \
                              (dst) + r_ * PADU + c_ * 4);                    \
            asm volatile("cp.async.ca.shared.global [%0], [%1], 16;\n"        \
                         :: "r"(d_), "l"(src_));                              \
        }                                                                     \
    } while (0)

    if (t < KW_TILES) LOAD_TILE(bufs[0], t);
    asm volatile("cp.async.commit_group;\n");

    while (t < KW_TILES) {
        int tn = t + KW_GRID;
        if (tn < KW_TILES) LOAD_TILE(bufs[cur ^ 1], tn);
        asm volatile("cp.async.commit_group;\n");
        asm volatile("cp.async.wait_group 1;\n");
        __syncthreads();

        uint32_t* sA = bufs[cur];
        float acc[2][8][4];
#pragma unroll
        for (int mi = 0; mi < 2; mi++)
#pragma unroll
            for (int ni = 0; ni < 8; ni++)
#pragma unroll
                for (int j = 0; j < 4; j++) acc[mi][ni][j] = 0.f;

#pragma unroll
        for (int ks = 0; ks < 8; ks++) {
            const int p0 = ks * 8;
            uint32_t a[2][4];
#pragma unroll
            for (int mi = 0; mi < 2; mi++) {
                int r = stripe + mi * 16 + gid;
                a[mi][0] = sA[r * PADU + p0 + tig];
                a[mi][1] = sA[(r + 8) * PADU + p0 + tig];
                a[mi][2] = sA[r * PADU + p0 + tig + 4];
                a[mi][3] = sA[(r + 8) * PADU + p0 + tig + 4];
            }
            uint32_t bf[8][2];
#pragma unroll
            for (int ni = 0; ni < 8; ni++) {
                int n = colh + ni * 8 + gid;
                bf[ni][0] = sW[n * PADU + p0 + tig];
                bf[ni][1] = sW[n * PADU + p0 + tig + 4];
            }
#pragma unroll
            for (int mi = 0; mi < 2; mi++)
#pragma unroll
                for (int ni = 0; ni < 8; ni++) {
                    asm volatile(
                        "mma.sync.aligned.m16n8k16.row.col.f32.bf16.bf16.f32 "
                        "{%0,%1,%2,%3}, {%4,%5,%6,%7}, {%8,%9}, {%0,%1,%2,%3};"
                        : "+f"(acc[mi][ni][0]), "+f"(acc[mi][ni][1]),
                          "+f"(acc[mi][ni][2]), "+f"(acc[mi][ni][3])
                        : "r"(a[mi][0]), "r"(a[mi][1]), "r"(a[mi][2]), "r"(a[mi][3]),
                          "r"(bf[ni][0]), "r"(bf[ni][1]));
                }
        }

        // epilogue: bf16 pack + store
        const int row0 = t * 128;
        uint32_t* kw32 = (uint32_t*)g_KWh;
#pragma unroll
        for (int mi = 0; mi < 2; mi++) {
            int r0 = row0 + stripe + mi * 16 + gid;
            int r1 = r0 + 8;
#pragma unroll
            for (int ni = 0; ni < 8; ni++) {
                int c = colh + ni * 8 + tig * 2;
                if (r0 <= NITEMS) {
                    __nv_bfloat162 h = __floats2bfloat162_rn(acc[mi][ni][0], acc[mi][ni][1]);
                    kw32[(size_t)r0 * (Dd / 2) + (c >> 1)] = *(uint32_t*)&h;
                }
                if (r1 <= NITEMS) {
                    __nv_bfloat162 h = __floats2bfloat162_rn(acc[mi][ni][2], acc[mi][ni][3]);
                    kw32[(size_t)r1 * (Dd / 2) + (c >> 1)] = *(uint32_t*)&h;
                }
            }
        }
        __syncthreads();
        cur ^= 1;
        t = tn;
    }
#undef LOAD_TILE
}

// ------------------------------------------- Kernel B: Q = g_Uh @ Wq + b_att (bf16 MMA)
__global__ __launch_bounds__(256) void q_kernel(const float* __restrict__ Wq,
                                                const float* __restrict__ b_att) {
    extern __shared__ uint32_t smem_u[];
    uint32_t* sW = smem_u;                 // [128][68]
    uint32_t* sA = smem_u + 128 * PADU;    // [128][68]

    const int tid  = threadIdx.x;
    const int lane = tid & 31;
    const int wid  = tid >> 5;
    const int gid  = lane >> 2;
    const int tig  = lane & 3;
    const int stripe = (wid & 3) * 32;
    const int colh   = (wid >> 2) * 64;
    const int row0   = blockIdx.x * 128;

    for (int i = tid; i < 128 * 64; i += 256) {
        int n = i >> 6, p = i & 63;
        __nv_bfloat162 h = __floats2bfloat162_rn(Wq[(2 * p) * Dd + n],
                                                 Wq[(2 * p + 1) * Dd + n]);
        sW[n * PADU + p] = *(uint32_t*)&h;
    }
    for (int i = tid; i < 128 * 64; i += 256) {
        int r = i >> 6, p = i & 63;
        sA[r * PADU + p] = ((const uint32_t*)g_Uh)[(size_t)(row0 + r) * 64 + p];
    }
    __syncthreads();

    float acc[2][8][4];
#pragma unroll
    for (int mi = 0; mi < 2; mi++)
#pragma unroll
        for (int ni = 0; ni < 8; ni++)
#pragma unroll
            for (int j = 0; j < 4; j++) acc[mi][ni][j] = 0.f;

#pragma unroll
    for (int ks = 0; ks < 8; ks++) {
        const int p0 = ks * 8;
        uint32_t a[2][4];
#pragma unroll
        for (int mi = 0; mi < 2; mi++) {
            int r = stripe + mi * 16 + gid;
            a[mi][0] = sA[r * PADU + p0 + tig];
            a[mi][1] = sA[(r + 8) * PADU + p0 + tig];
            a[mi][2] = sA[r * PADU + p0 + tig + 4];
            a[mi][3] = sA[(r + 8) * PADU + p0 + tig + 4];
        }
        uint32_t bf[8][2];
#pragma unroll
        for (int ni = 0; ni < 8; ni++) {
            int n = colh + ni * 8 + gid;
            bf[ni][0] = sW[n * PADU + p0 + tig];
            bf[ni][1] = sW[n * PADU + p0 + tig + 4];
        }
#pragma unroll
        for (int mi = 0; mi < 2; mi++)
#pragma unroll
            for (int ni = 0; ni < 8; ni++) {
                asm volatile(
                    "mma.sync.aligned.m16n8k16.row.col.f32.bf16.bf16.f32 "
                    "{%0,%1,%2,%3}, {%4,%5,%6,%7}, {%8,%9}, {%0,%1,%2,%3};"
                    : "+f"(acc[mi][ni][0]), "+f"(acc[mi][ni][1]),
                      "+f"(acc[mi][ni][2]), "+f"(acc[mi][ni][3])
                    : "r"(a[mi][0]), "r"(a[mi][1]), "r"(a[mi][2]), "r"(a[mi][3]),
                      "r"(bf[ni][0]), "r"(bf[ni][1]));
            }
    }

#pragma unroll
    for (int mi = 0; mi < 2; mi++) {
        int r0 = row0 + stripe + mi * 16 + gid;
        int r1 = r0 + 8;
#pragma unroll
        for (int ni = 0; ni < 8; ni++) {
            int c = colh + ni * 8 + tig * 2;
            float2 ba = *(const float2*)(b_att + c);
            *(float2*)(g_Q + (size_t)r0 * Dd + c) =
                make_float2(acc[mi][ni][0] + ba.x, acc[mi][ni][1] + ba.y);
            *(float2*)(g_Q + (size_t)r1 * Dd + c) =
                make_float2(acc[mi][ni][2] + ba.x, acc[mi][ni][3] + ba.y);
        }
    }
}

// ------------------------------------------- Kernel C: fused BAM forward
__global__ __launch_bounds__(128) void fused_kernel(
    const float* __restrict__ user_emb,
    const float* __restrict__ item_emb,
    const float* __restrict__ v_att,
    const float* __restrict__ ln_u_g, const float* __restrict__ ln_u_b,
    const float* __restrict__ ln_i_g, const float* __restrict__ ln_i_b,
    const float* __restrict__ pred_W, const float* __restrict__ pred_b,
    const int* __restrict__ user_hist,
    const int* __restrict__ user_idx,
    const int* __restrict__ item_idx,
    float* __restrict__ out)
{
    __shared__ __align__(16) float sh_q[Dd];
    __shared__ __align__(16) float sh_u[Dd];
    __shared__ __align__(16) float sh_v[Dd];
    __shared__ int   sh_r[Ll];
    __shared__ float sh_s[Ll];
    __shared__ float sh_w1[Ll];
    __shared__ float sh_w2[Ll];
    __shared__ float red[4];

    const int tid  = threadIdx.x;
    const int lane = tid & 31;
    const int wrp  = tid >> 5;
    const int b    = blockIdx.x;
    const int uidx = user_idx[b];
    const int tgt  = item_idx[b];

    sh_u[tid] = user_emb[(size_t)uidx * Dd + tid];
    sh_q[tid] = g_Q[(size_t)b * Dd + tid];     // includes b_att
    sh_v[tid] = v_att[tid];
    float validf = 0.f;
    for (int l = tid; l < Ll; l += 128) {
        int r = user_hist[(size_t)uidx * Ll + l];
        bool ok = (r != tgt) && (r != NITEMS);
        sh_r[l] = ok ? r : -1;
        validf += ok ? 1.f : 0.f;
    }
    __syncthreads();

    float nvf = breduce_sum(validf, red);
    int n_valid = (int)(nvf + 0.5f);
    float nv_clamped = (n_valid > 0) ? (float)n_valid : 1.0f;
    float mu_p = -logf(nv_clamped);

    // scores: warp per l, 2 rows per iteration; lane covers 4 dims (8B bf16)
    float4 q4, v4;
    {
        float2 qa = *(const float2*)(sh_q + lane * 4);
        float2 qb = *(const float2*)(sh_q + lane * 4 + 2);
        q4 = make_float4(qa.x, qa.y, qb.x, qb.y);
        float2 va = *(const float2*)(sh_v + lane * 4);
        float2 vb = *(const float2*)(sh_v + lane * 4 + 2);
        v4 = make_float4(va.x, va.y, vb.x, vb.y);
    }
    for (int l = wrp; l < Ll; l += 8) {
        int l1 = l + 4;
        int r0 = sh_r[l];
        int r1 = (l1 < Ll) ? sh_r[l1] : -1;
        uint2 raw0 = make_uint2(0u, 0u), raw1 = make_uint2(0u, 0u);
        if (r0 >= 0)
            raw0 = ((const uint2*)(g_KWh + (size_t)r0 * Dd))[lane];
        if (r1 >= 0)
            raw1 = ((const uint2*)(g_KWh + (size_t)r1 * Dd))[lane];

#pragma unroll
        for (int j = 0; j < 2; j++) {
            int rr = j ? r1 : r0;
            int ll = j ? l1 : l;
            if (ll >= Ll) break;
            float sval = -1e30f;
            if (rr >= 0) {
                uint2 raw = j ? raw1 : raw0;
                float2 f0 = __bfloat1622float2(*(__nv_bfloat162*)&raw.x);
                float2 f1 = __bfloat1622float2(*(__nv_bfloat162*)&raw.y);
                float tv = v4.x * fast_tanh(q4.x + f0.x);
                tv = fmaf(v4.y, fast_tanh(q4.y + f0.y), tv);
                tv = fmaf(v4.z, fast_tanh(q4.z + f1.x), tv);
                tv = fmaf(v4.w, fast_tanh(q4.w + f1.y), tv);
#pragma unroll
                for (int o = 16; o; o >>= 1)
                    tv += __shfl_down_sync(0xffffffffu, tv, o);
                sval = tv * 0.25f;   // / TAU
            }
            if (lane == 0) sh_s[ll] = sval;
        }
    }
    __syncthreads();

    // softmax
    float m = -1e30f;
    for (int l = tid; l < Ll; l += 128) m = fmaxf(m, sh_s[l]);
    m = breduce_max(m, red);

    float esum = 0.f;
    for (int l = tid; l < Ll; l += 128) {
        float e = 0.f;
        if (sh_r[l] >= 0) e = expf(sh_s[l] - m);
        sh_s[l] = e;
        esum += e;
    }
    esum = breduce_sum(esum, red);
    float inv_es = (esum > 0.f) ? (1.0f / esum) : 0.f;

    // lognormal sampling (exact JAX partitionable threefry) + KL
    float klacc = 0.f;
    for (int l = tid; l < Ll; l += 128) {
        float w1 = 0.f, w2 = 0.f;
        if (sh_r[l] >= 0) {
            float alpha = sh_s[l] * inv_es;
            float mu = logf(alpha + 1e-24f);
            uint32_t idx = (uint32_t)(b * Ll + l);
            float e1 = jax_normal(1u, idx);
            float e2 = jax_normal(2u, idx);
            w1 = expf(fmaf(0.1f, e1, mu));
            w2 = expf(fmaf(0.1f, e2, mu));
            float dmu = mu - mu_p;
            klacc += 1.8075851f + 0.5f * dmu * dmu;  // log(10)-0.5+SIG_Q^2/2 + d^2/2
        }
        sh_w1[l] = w1;
        sh_w2[l] = w2;
    }
    float klsum = breduce_sum(klacc, red);
    if (tid == 0) { g_klp[b] = klsum; g_cnt[b] = n_valid; }

    float s1 = 0.f, s2 = 0.f;
    for (int l = tid; l < Ll; l += 128) { s1 += sh_w1[l]; s2 += sh_w2[l]; }
    float S1 = breduce_sum(s1, red);
    float S2 = breduce_sum(s2, red);
    float i1 = 1.0f / (S1 + 1e-12f);
    float i2 = 1.0f / (S2 + 1e-12f);

    // contexts: fp32 item_emb gather (value path must stay fp32!),
    // 4 batched loads per group; one gather serves both draws
    float cu = 0.f, ci = 0.f;
    for (int l0 = 0; l0 < Ll; l0 += 4) {
        float vv[4];
#pragma unroll
        for (int j = 0; j < 4; j++) {
            int r = sh_r[l0 + j];
            vv[j] = (r >= 0) ? item_emb[(size_t)r * Dd + tid] : 0.f;
        }
#pragma unroll
        for (int j = 0; j < 4; j++) {
            cu = fmaf(sh_w1[l0 + j], vv[j], cu);
            ci = fmaf(sh_w2[l0 + j], vv[j], ci);
        }
    }
    cu *= i1; ci *= i2;

    // layernorm(u ctx * user_emb)
    float xu = cu * sh_u[tid];
    float mean_u = breduce_sum(xu, red) * (1.0f / Dd);
    float du = xu - mean_u;
    float var_u = breduce_sum(du * du, red) * (1.0f / Dd);
    float us = du * rsqrtf(var_u + 1e-5f) * ln_u_g[tid] + ln_u_b[tid];

    // layernorm(i ctx * item_emb[target])
    float xi = ci * item_emb[(size_t)tgt * Dd + tid];
    float mean_i = breduce_sum(xi, red) * (1.0f / Dd);
    float di = xi - mean_i;
    float var_i = breduce_sum(di * di, red) * (1.0f / Dd);
    float is_ = di * rsqrtf(var_i + 1e-5f) * ln_i_g[tid] + ln_i_b[tid];

    float pv = us * is_ * pred_W[tid];
    float dot = breduce_sum(pv, red);
    if (tid == 0) out[b] = dot + pred_b[0];
}

// ------------------------------------------- Kernel D: deterministic KL reduce
__global__ __launch_bounds__(256) void kl_reduce_kernel(float* __restrict__ out,
                                                        int out_size) {
    __shared__ float rs[8];
    __shared__ int   ri[8];
    int tid = threadIdx.x;
    float s = 0.f; int c = 0;
    for (int i = tid; i < Bb; i += 256) { s += g_klp[i]; c += g_cnt[i]; }
#pragma unroll
    for (int o = 16; o; o >>= 1) {
        s += __shfl_down_sync(0xffffffffu, s, o);
        c += __shfl_down_sync(0xffffffffu, c, o);
    }
    if ((tid & 31) == 0) { rs[tid >> 5] = s; ri[tid >> 5] = c; }
    __syncthreads();
    if (tid == 0) {
        float S = 0.f; int C = 0;
        for (int i = 0; i < 8; i++) { S += rs[i]; C += ri[i]; }
        if (C < 1) C = 1;
        float kl = 0.25f * S / (float)C;   // BETA * sum / cnt ; (kl_u+kl_i)/2 == kl_u
        if (out_size > Bb) out[Bb] = kl;
    }
}

// ------------------------------------------- launcher
extern "C" void kernel_launch(void* const* d_in, const int* in_sizes, int n_in,
                              void* d_out, int out_size) {
    const float* user_emb = (const float*)d_in[0];
    const float* item_emb = (const float*)d_in[1];
    const float* Wq       = (const float*)d_in[2];
    const float* Wk       = (const float*)d_in[3];
    const float* b_att    = (const float*)d_in[4];
    const float* v_att    = (const float*)d_in[5];
    const float* ln_u_g   = (const float*)d_in[6];
    const float* ln_u_b   = (const float*)d_in[7];
    const float* ln_i_g   = (const float*)d_in[8];
    const float* ln_i_b   = (const float*)d_in[9];
    const float* pred_W   = (const float*)d_in[10];
    const float* pred_b   = (const float*)d_in[11];
    const int* user_hist  = (const int*)d_in[12];
    const int* user_idx   = (const int*)d_in[13];
    const int* item_idx   = (const int*)d_in[14];
    float* out = (float*)d_out;

    const int kw_smem = 3 * 128 * PADU * 4;   // 104448 B
    const int q_smem  = 2 * 128 * PADU * 4;   // 69632 B
    cudaFuncSetAttribute(kw_kernel, cudaFuncAttributeMaxDynamicSharedMemorySize,
                         kw_smem);
    cudaFuncSetAttribute(q_kernel, cudaFuncAttributeMaxDynamicSharedMemorySize,
                         q_smem);

    conv_item_kernel<<<1184, 256>>>(item_emb);
    conv_user_kernel<<<148, 256>>>(user_emb, user_idx);
    kw_kernel<<<KW_GRID, 256, kw_smem>>>(Wk);
    q_kernel<<<Bb / 128, 256, q_smem>>>(Wq, b_att);
    fused_kernel<<<Bb, 128>>>(user_emb, item_emb, v_att,
                              ln_u_g, ln_u_b, ln_i_g, ln_i_b,
                              pred_W, pred_b, user_hist, user_idx, item_idx, out);
    kl_reduce_kernel<<<1, 256>>>(out, out_size);
}

// round 8
// speedup vs baseline: 1.0911x; 1.0911x over previous
#include <cuda_runtime.h>
#include <cuda_bf16.h>
#include <stdint.h>

#define Dd 128
#define Ll 200
#define Bb 4096
#define NITEMS 100000

// Scratch (static device globals: allocation-free per harness rules)
__device__ __nv_bfloat16 g_KWh[(NITEMS + 1) * Dd];  // item_emb @ Wk (bf16)
__device__ __nv_bfloat16 g_Ih[(NITEMS + 1) * Dd];   // item_emb in bf16 (GEMM input only)
__device__ float g_Q[Bb * Dd];                      // Q = u@Wq + b_att (fp32)
__device__ float g_F1[Bb * Ll];                     // exp(0.1*eps1)
__device__ float g_F2[Bb * Ll];                     // exp(0.1*eps2)
__device__ float g_klp[Bb];
__device__ int   g_cnt[Bb];

// ---------------------------------------------------------------- utilities

__device__ __forceinline__ uint32_t rotl32(uint32_t x, int d) {
    return (x << d) | (x >> (32 - d));
}

// Exact JAX threefry2x32 (20 rounds)
__device__ __forceinline__ void threefry2x32(uint32_t k0, uint32_t k1,
                                             uint32_t c0, uint32_t c1,
                                             uint32_t& o0, uint32_t& o1) {
    uint32_t ks2 = k0 ^ k1 ^ 0x1BD11BDAu;
    uint32_t x0 = c0 + k0, x1 = c1 + k1;
#define TF_R(r) { x0 += x1; x1 = rotl32(x1, r); x1 ^= x0; }
    TF_R(13) TF_R(15) TF_R(26) TF_R(6)  x0 += k1;  x1 += ks2 + 1u;
    TF_R(17) TF_R(29) TF_R(16) TF_R(24) x0 += ks2; x1 += k0 + 2u;
    TF_R(13) TF_R(15) TF_R(26) TF_R(6)  x0 += k0;  x1 += k1 + 3u;
    TF_R(17) TF_R(29) TF_R(16) TF_R(24) x0 += k1;  x1 += ks2 + 4u;
    TF_R(13) TF_R(15) TF_R(26) TF_R(6)  x0 += ks2; x1 += k0 + 5u;
#undef TF_R
    o0 = x0; o1 = x1;
}

// jax.random.normal under jax_threefry_partitionable=True:
//   counter = 64-bit flat index -> (c0 = 0, c1 = idx); 32-bit draw = o0 ^ o1
__device__ __forceinline__ float jax_normal(uint32_t k1, uint32_t idx) {
    uint32_t o0, o1;
    threefry2x32(0u, k1, 0u, idx, o0, o1);
    uint32_t bits = o0 ^ o1;
    float f = __uint_as_float((bits >> 9) | 0x3F800000u) - 1.0f;  // [0,1)
    const float LO = -0.99999994f;                                // nextafter(-1,0)
    float u = fmaf(f, 2.0f, LO);
    u = fmaxf(u, LO);
    return 1.41421356f * erfinvf(u);
}

__device__ __forceinline__ float fast_tanh(float x) {
    float y;
    asm("tanh.approx.f32 %0, %1;" : "=f"(y) : "f"(x));
    return y;
}

__device__ __forceinline__ float breduce_sum(float v, volatile float* red) {
    int tid = threadIdx.x, lane = tid & 31, wrp = tid >> 5;
#pragma unroll
    for (int o = 16; o; o >>= 1) v += __shfl_down_sync(0xffffffffu, v, o);
    if (lane == 0) red[wrp] = v;
    __syncthreads();
    float r = (red[0] + red[1]) + (red[2] + red[3]);
    __syncthreads();
    return r;
}

__device__ __forceinline__ float breduce_max(float v, volatile float* red) {
    int tid = threadIdx.x, lane = tid & 31, wrp = tid >> 5;
#pragma unroll
    for (int o = 16; o; o >>= 1) v = fmaxf(v, __shfl_down_sync(0xffffffffu, v, o));
    if (lane == 0) red[wrp] = v;
    __syncthreads();
    float r = fmaxf(fmaxf(red[0], red[1]), fmaxf(red[2], red[3]));
    __syncthreads();
    return r;
}

// ------------------------------------------- Kernel 0: item_emb -> bf16 table
__global__ __launch_bounds__(256) void conv_item_kernel(const float* __restrict__ item_emb) {
    const int total = (NITEMS + 1) * (Dd / 4);          // float4 count
    for (int i = blockIdx.x * 256 + threadIdx.x; i < total; i += gridDim.x * 256) {
        float4 v = ((const float4*)item_emb)[i];
        __nv_bfloat162 lo = __floats2bfloat162_rn(v.x, v.y);
        __nv_bfloat162 hi = __floats2bfloat162_rn(v.z, v.w);
        uint2 p;
        p.x = *(uint32_t*)&lo;
        p.y = *(uint32_t*)&hi;
        ((uint2*)g_Ih)[i] = p;
    }
}

// ------------------------------------------- Kernel E: precompute lognormal factors
// F = exp(SIG_Q * eps) with exact JAX partitionable threefry; data-independent.
__global__ __launch_bounds__(256) void eps_kernel() {
    int idx = blockIdx.x * 256 + threadIdx.x;
    if (idx < Bb * Ll) {
        float e1 = jax_normal(1u, (uint32_t)idx);
        float e2 = jax_normal(2u, (uint32_t)idx);
        g_F1[idx] = expf(0.1f * e1);
        g_F2[idx] = expf(0.1f * e2);
    }
}

// =================================================================
// bf16 m16n8k16 MMA; smem tiles: uint32 k-pairs, row stride PADU uint32
// =================================================================
#define PADU 68

// ------------------------------------------- Kernel A: KW = item_emb @ Wk (bf16 MMA)
// Persistent 148 blocks x 256 thr (8 warps), 2 blocks/SM.
// 128-row A tiles double-buffered via cp.async from g_Ih.
#define KW_GRID 148
#define KW_TILES ((NITEMS + 1 + 127) / 128)   // 782

__global__ __launch_bounds__(256, 2) void kw_kernel(const float* __restrict__ Wk) {
    extern __shared__ uint32_t smem_u[];
    uint32_t* sW  = smem_u;                    // [128 n][68]
    uint32_t* sA0 = smem_u + 128 * PADU;
    uint32_t* sA1 = sA0 + 128 * PADU;

    const int tid  = threadIdx.x;
    const int lane = tid & 31;
    const int wid  = tid >> 5;
    const int gid  = lane >> 2;      // 0..7
    const int tig  = lane & 3;       // 0..3
    const int stripe = (wid & 3) * 32;
    const int colh   = (wid >> 2) * 64;

    // sW[n][p] = {bf16(Wk[2p][n]), bf16(Wk[2p+1][n])}
    for (int i = tid; i < 128 * 64; i += 256) {
        int n = i >> 6, p = i & 63;
        __nv_bfloat162 h = __floats2bfloat162_rn(Wk[(2 * p) * Dd + n],
                                                 Wk[(2 * p + 1) * Dd + n]);
        sW[n * PADU + p] = *(uint32_t*)&h;
    }

    uint32_t* bufs[2] = { sA0, sA1 };
    int cur = 0;
    int t = blockIdx.x;

    // async tile loader: 128 rows x 16 16B-chunks (bf16 rows = 256B)
#define LOAD_TILE(dst, tt) do {                                               \
        const int row0_ = (tt) * 128;                                         \
        for (int i = tid; i < 128 * 16; i += 256) {                           \
            int r_ = i >> 4, c_ = i & 15;                                     \
            int sr_ = row0_ + r_; if (sr_ > NITEMS) sr_ = NITEMS;             \
            const char* src_ = (const char*)g_Ih + (size_t)sr_ * 256 + c_ * 16;\
            uint32_t d_ = (uint32_t)__cvta_generic_to_shared(                 \
                              (dst) + r_ * PADU + c_ * 4);                    \
            asm volatile("cp.async.ca.shared.global [%0], [%1], 16;\n"        \
                         :: "r"(d_), "l"(src_));                              \
        }                                                                     \
    } while (0)

    if (t < KW_TILES) LOAD_TILE(bufs[0], t);
    asm volatile("cp.async.commit_group;\n");

    while (t < KW_TILES) {
        int tn = t + KW_GRID;
        if (tn < KW_TILES) LOAD_TILE(bufs[cur ^ 1], tn);
        asm volatile("cp.async.commit_group;\n");
        asm volatile("cp.async.wait_group 1;\n");
        __syncthreads();

        uint32_t* sA = bufs[cur];
        float acc[2][8][4];
#pragma unroll
        for (int mi = 0; mi < 2; mi++)
#pragma unroll
            for (int ni = 0; ni < 8; ni++)
#pragma unroll
                for (int j = 0; j < 4; j++) acc[mi][ni][j] = 0.f;

#pragma unroll
        for (int ks = 0; ks < 8; ks++) {
            const int p0 = ks * 8;
            uint32_t a[2][4];
#pragma unroll
            for (int mi = 0; mi < 2; mi++) {
                int r = stripe + mi * 16 + gid;
                a[mi][0] = sA[r * PADU + p0 + tig];
                a[mi][1] = sA[(r + 8) * PADU + p0 + tig];
                a[mi][2] = sA[r * PADU + p0 + tig + 4];
                a[mi][3] = sA[(r + 8) * PADU + p0 + tig + 4];
            }
            uint32_t bf[8][2];
#pragma unroll
            for (int ni = 0; ni < 8; ni++) {
                int n = colh + ni * 8 + gid;
                bf[ni][0] = sW[n * PADU + p0 + tig];
                bf[ni][1] = sW[n * PADU + p0 + tig + 4];
            }
#pragma unroll
            for (int mi = 0; mi < 2; mi++)
#pragma unroll
                for (int ni = 0; ni < 8; ni++) {
                    asm volatile(
                        "mma.sync.aligned.m16n8k16.row.col.f32.bf16.bf16.f32 "
                        "{%0,%1,%2,%3}, {%4,%5,%6,%7}, {%8,%9}, {%0,%1,%2,%3};"
                        : "+f"(acc[mi][ni][0]), "+f"(acc[mi][ni][1]),
                          "+f"(acc[mi][ni][2]), "+f"(acc[mi][ni][3])
                        : "r"(a[mi][0]), "r"(a[mi][1]), "r"(a[mi][2]), "r"(a[mi][3]),
                          "r"(bf[ni][0]), "r"(bf[ni][1]));
                }
        }

        // epilogue: bf16 pack + store
        const int row0 = t * 128;
        uint32_t* kw32 = (uint32_t*)g_KWh;
#pragma unroll
        for (int mi = 0; mi < 2; mi++) {
            int r0 = row0 + stripe + mi * 16 + gid;
            int r1 = r0 + 8;
#pragma unroll
            for (int ni = 0; ni < 8; ni++) {
                int c = colh + ni * 8 + tig * 2;
                if (r0 <= NITEMS) {
                    __nv_bfloat162 h = __floats2bfloat162_rn(acc[mi][ni][0], acc[mi][ni][1]);
                    kw32[(size_t)r0 * (Dd / 2) + (c >> 1)] = *(uint32_t*)&h;
                }
                if (r1 <= NITEMS) {
                    __nv_bfloat162 h = __floats2bfloat162_rn(acc[mi][ni][2], acc[mi][ni][3]);
                    kw32[(size_t)r1 * (Dd / 2) + (c >> 1)] = *(uint32_t*)&h;
                }
            }
        }
        __syncthreads();
        cur ^= 1;
        t = tn;
    }
#undef LOAD_TILE
}

// ------------------------------------------- Kernel B: Q = user_emb[uidx] @ Wq + b_att
// 128 blocks x 256 thr; 32-row tiles; user gather + bf16 convert fused in.
// Warp w: m-rows (w&1)*16..+16, n-cols (w>>1)*32..+32 (1 m-frag x 4 n8 tiles).
__global__ __launch_bounds__(256) void q_kernel(const float* __restrict__ user_emb,
                                                const int* __restrict__ user_idx,
                                                const float* __restrict__ Wq,
                                                const float* __restrict__ b_att) {
    extern __shared__ uint32_t smem_u[];
    uint32_t* sW = smem_u;                 // [128 n][68]
    uint32_t* sA = smem_u + 128 * PADU;    // [32 m][68]

    const int tid  = threadIdx.x;
    const int lane = tid & 31;
    const int wid  = tid >> 5;
    const int gid  = lane >> 2;
    const int tig  = lane & 3;
    const int mrow = (wid & 1) * 16;
    const int ncol = (wid >> 1) * 32;
    const int row0 = blockIdx.x * 32;

    for (int i = tid; i < 128 * 64; i += 256) {
        int n = i >> 6, p = i & 63;
        __nv_bfloat162 h = __floats2bfloat162_rn(Wq[(2 * p) * Dd + n],
                                                 Wq[(2 * p + 1) * Dd + n]);
        sW[n * PADU + p] = *(uint32_t*)&h;
    }
    for (int i = tid; i < 32 * 64; i += 256) {
        int r = i >> 6, p = i & 63;
        int u = user_idx[row0 + r];
        float2 v = *(const float2*)(user_emb + (size_t)u * Dd + 2 * p);
        __nv_bfloat162 h = __floats2bfloat162_rn(v.x, v.y);
        sA[r * PADU + p] = *(uint32_t*)&h;
    }
    __syncthreads();

    float acc[4][4];
#pragma unroll
    for (int ni = 0; ni < 4; ni++)
#pragma unroll
        for (int j = 0; j < 4; j++) acc[ni][j] = 0.f;

#pragma unroll
    for (int ks = 0; ks < 8; ks++) {
        const int p0 = ks * 8;
        uint32_t a[4];
        a[0] = sA[(mrow + gid) * PADU + p0 + tig];
        a[1] = sA[(mrow + 8 + gid) * PADU + p0 + tig];
        a[2] = sA[(mrow + gid) * PADU + p0 + tig + 4];
        a[3] = sA[(mrow + 8 + gid) * PADU + p0 + tig + 4];
        uint32_t bf[4][2];
#pragma unroll
        for (int ni = 0; ni < 4; ni++) {
            int n = ncol + ni * 8 + gid;
            bf[ni][0] = sW[n * PADU + p0 + tig];
            bf[ni][1] = sW[n * PADU + p0 + tig + 4];
        }
#pragma unroll
        for (int ni = 0; ni < 4; ni++) {
            asm volatile(
                "mma.sync.aligned.m16n8k16.row.col.f32.bf16.bf16.f32 "
                "{%0,%1,%2,%3}, {%4,%5,%6,%7}, {%8,%9}, {%0,%1,%2,%3};"
                : "+f"(acc[ni][0]), "+f"(acc[ni][1]),
                  "+f"(acc[ni][2]), "+f"(acc[ni][3])
                : "r"(a[0]), "r"(a[1]), "r"(a[2]), "r"(a[3]),
                  "r"(bf[ni][0]), "r"(bf[ni][1]));
        }
    }

    {
        int r0 = row0 + mrow + gid;
        int r1 = r0 + 8;
#pragma unroll
        for (int ni = 0; ni < 4; ni++) {
            int c = ncol + ni * 8 + tig * 2;
            float2 ba = *(const float2*)(b_att + c);
            *(float2*)(g_Q + (size_t)r0 * Dd + c) =
                make_float2(acc[ni][0] + ba.x, acc[ni][1] + ba.y);
            *(float2*)(g_Q + (size_t)r1 * Dd + c) =
                make_float2(acc[ni][2] + ba.x, acc[ni][3] + ba.y);
        }
    }
}

// ------------------------------------------- Kernel C: fused BAM forward
// RNG hoisted out; __launch_bounds__(128, 8) for 8 blocks/SM occupancy.
__global__ __launch_bounds__(128, 8) void fused_kernel(
    const float* __restrict__ user_emb,
    const float* __restrict__ item_emb,
    const float* __restrict__ v_att,
    const float* __restrict__ ln_u_g, const float* __restrict__ ln_u_b,
    const float* __restrict__ ln_i_g, const float* __restrict__ ln_i_b,
    const float* __restrict__ pred_W, const float* __restrict__ pred_b,
    const int* __restrict__ user_hist,
    const int* __restrict__ user_idx,
    const int* __restrict__ item_idx,
    float* __restrict__ out)
{
    __shared__ __align__(16) float sh_q[Dd];
    __shared__ __align__(16) float sh_u[Dd];
    __shared__ __align__(16) float sh_v[Dd];
    __shared__ int   sh_r[Ll];
    __shared__ float sh_s[Ll];
    __shared__ float sh_w1[Ll];
    __shared__ float sh_w2[Ll];
    __shared__ float red[4];

    const int tid  = threadIdx.x;
    const int lane = tid & 31;
    const int wrp  = tid >> 5;
    const int b    = blockIdx.x;
    const int uidx = user_idx[b];
    const int tgt  = item_idx[b];

    sh_u[tid] = user_emb[(size_t)uidx * Dd + tid];
    sh_q[tid] = g_Q[(size_t)b * Dd + tid];     // includes b_att
    sh_v[tid] = v_att[tid];
    float validf = 0.f;
    for (int l = tid; l < Ll; l += 128) {
        int r = user_hist[(size_t)uidx * Ll + l];
        bool ok = (r != tgt) && (r != NITEMS);
        sh_r[l] = ok ? r : -1;
        validf += ok ? 1.f : 0.f;
    }
    __syncthreads();

    float nvf = breduce_sum(validf, red);
    int n_valid = (int)(nvf + 0.5f);
    float nv_clamped = (n_valid > 0) ? (float)n_valid : 1.0f;
    float mu_p = -logf(nv_clamped);

    // scores: warp per l, 2 rows per iteration; lane covers 4 dims (8B bf16)
    float4 q4, v4;
    {
        float2 qa = *(const float2*)(sh_q + lane * 4);
        float2 qb = *(const float2*)(sh_q + lane * 4 + 2);
        q4 = make_float4(qa.x, qa.y, qb.x, qb.y);
        float2 va = *(const float2*)(sh_v + lane * 4);
        float2 vb = *(const float2*)(sh_v + lane * 4 + 2);
        v4 = make_float4(va.x, va.y, vb.x, vb.y);
    }
    for (int l = wrp; l < Ll; l += 8) {
        int l1 = l + 4;
        int r0 = sh_r[l];
        int r1 = (l1 < Ll) ? sh_r[l1] : -1;
        uint2 raw0 = make_uint2(0u, 0u), raw1 = make_uint2(0u, 0u);
        if (r0 >= 0)
            raw0 = ((const uint2*)(g_KWh + (size_t)r0 * Dd))[lane];
        if (r1 >= 0)
            raw1 = ((const uint2*)(g_KWh + (size_t)r1 * Dd))[lane];

#pragma unroll
        for (int j = 0; j < 2; j++) {
            int rr = j ? r1 : r0;
            int ll = j ? l1 : l;
            if (ll >= Ll) break;
            float sval = -1e30f;
            if (rr >= 0) {
                uint2 raw = j ? raw1 : raw0;
                float2 f0 = __bfloat1622float2(*(__nv_bfloat162*)&raw.x);
                float2 f1 = __bfloat1622float2(*(__nv_bfloat162*)&raw.y);
                float tv = v4.x * fast_tanh(q4.x + f0.x);
                tv = fmaf(v4.y, fast_tanh(q4.y + f0.y), tv);
                tv = fmaf(v4.z, fast_tanh(q4.z + f1.x), tv);
                tv = fmaf(v4.w, fast_tanh(q4.w + f1.y), tv);
#pragma unroll
                for (int o = 16; o; o >>= 1)
                    tv += __shfl_down_sync(0xffffffffu, tv, o);
                sval = tv * 0.25f;   // / TAU
            }
            if (lane == 0) sh_s[ll] = sval;
        }
    }
    __syncthreads();

    // softmax
    float m = -1e30f;
    for (int l = tid; l < Ll; l += 128) m = fmaxf(m, sh_s[l]);
    m = breduce_max(m, red);

    float esum = 0.f;
    for (int l = tid; l < Ll; l += 128) {
        float e = 0.f;
        if (sh_r[l] >= 0) e = expf(sh_s[l] - m);
        sh_s[l] = e;
        esum += e;
    }
    esum = breduce_sum(esum, red);
    float inv_es = (esum > 0.f) ? (1.0f / esum) : 0.f;

    // sampled weights via precomputed lognormal factors + KL
    float klacc = 0.f;
    for (int l = tid; l < Ll; l += 128) {
        float w1 = 0.f, w2 = 0.f;
        if (sh_r[l] >= 0) {
            float alpha = sh_s[l] * inv_es;
            float ap = alpha + 1e-24f;
            float mu = logf(ap);
            int idx = b * Ll + l;
            w1 = ap * g_F1[idx];    // exp(mu)*exp(0.1 e1) == exp(mu+0.1 e1) to fp32 rounding
            w2 = ap * g_F2[idx];
            float dmu = mu - mu_p;
            klacc += 1.8075851f + 0.5f * dmu * dmu;  // log(10)-0.5+SIG_Q^2/2 + d^2/2
        }
        sh_w1[l] = w1;
        sh_w2[l] = w2;
    }
    float klsum = breduce_sum(klacc, red);
    if (tid == 0) { g_klp[b] = klsum; g_cnt[b] = n_valid; }

    float s1 = 0.f, s2 = 0.f;
    for (int l = tid; l < Ll; l += 128) { s1 += sh_w1[l]; s2 += sh_w2[l]; }
    float S1 = breduce_sum(s1, red);
    float S2 = breduce_sum(s2, red);
    float i1 = 1.0f / (S1 + 1e-12f);
    float i2 = 1.0f / (S2 + 1e-12f);

    // contexts: fp32 item_emb gather (value path stays fp32),
    // 4 batched loads per group; one gather serves both draws
    float cu = 0.f, ci = 0.f;
    for (int l0 = 0; l0 < Ll; l0 += 4) {
        float vv[4];
#pragma unroll
        for (int j = 0; j < 4; j++) {
            int r = sh_r[l0 + j];
            vv[j] = (r >= 0) ? item_emb[(size_t)r * Dd + tid] : 0.f;
        }
#pragma unroll
        for (int j = 0; j < 4; j++) {
            cu = fmaf(sh_w1[l0 + j], vv[j], cu);
            ci = fmaf(sh_w2[l0 + j], vv[j], ci);
        }
    }
    cu *= i1; ci *= i2;

    // layernorm(u ctx * user_emb)
    float xu = cu * sh_u[tid];
    float mean_u = breduce_sum(xu, red) * (1.0f / Dd);
    float du = xu - mean_u;
    float var_u = breduce_sum(du * du, red) * (1.0f / Dd);
    float us = du * rsqrtf(var_u + 1e-5f) * ln_u_g[tid] + ln_u_b[tid];

    // layernorm(i ctx * item_emb[target])
    float xi = ci * item_emb[(size_t)tgt * Dd + tid];
    float mean_i = breduce_sum(xi, red) * (1.0f / Dd);
    float di = xi - mean_i;
    float var_i = breduce_sum(di * di, red) * (1.0f / Dd);
    float is_ = di * rsqrtf(var_i + 1e-5f) * ln_i_g[tid] + ln_i_b[tid];

    float pv = us * is_ * pred_W[tid];
    float dot = breduce_sum(pv, red);
    if (tid == 0) out[b] = dot + pred_b[0];
}

// ------------------------------------------- Kernel D: deterministic KL reduce
__global__ __launch_bounds__(256) void kl_reduce_kernel(float* __restrict__ out,
                                                        int out_size) {
    __shared__ float rs[8];
    __shared__ int   ri[8];
    int tid = threadIdx.x;
    float s = 0.f; int c = 0;
    for (int i = tid; i < Bb; i += 256) { s += g_klp[i]; c += g_cnt[i]; }
#pragma unroll
    for (int o = 16; o; o >>= 1) {
        s += __shfl_down_sync(0xffffffffu, s, o);
        c += __shfl_down_sync(0xffffffffu, c, o);
    }
    if ((tid & 31) == 0) { rs[tid >> 5] = s; ri[tid >> 5] = c; }
    __syncthreads();
    if (tid == 0) {
        float S = 0.f; int C = 0;
        for (int i = 0; i < 8; i++) { S += rs[i]; C += ri[i]; }
        if (C < 1) C = 1;
        float kl = 0.25f * S / (float)C;   // BETA * sum / cnt ; (kl_u+kl_i)/2 == kl_u
        if (out_size > Bb) out[Bb] = kl;
    }
}

// ------------------------------------------- launcher
extern "C" void kernel_launch(void* const* d_in, const int* in_sizes, int n_in,
                              void* d_out, int out_size) {
    const float* user_emb = (const float*)d_in[0];
    const float* item_emb = (const float*)d_in[1];
    const float* Wq       = (const float*)d_in[2];
    const float* Wk       = (const float*)d_in[3];
    const float* b_att    = (const float*)d_in[4];
    const float* v_att    = (const float*)d_in[5];
    const float* ln_u_g   = (const float*)d_in[6];
    const float* ln_u_b   = (const float*)d_in[7];
    const float* ln_i_g   = (const float*)d_in[8];
    const float* ln_i_b   = (const float*)d_in[9];
    const float* pred_W   = (const float*)d_in[10];
    const float* pred_b   = (const float*)d_in[11];
    const int* user_hist  = (const int*)d_in[12];
    const int* user_idx   = (const int*)d_in[13];
    const int* item_idx   = (const int*)d_in[14];
    float* out = (float*)d_out;

    const int kw_smem = 3 * 128 * PADU * 4;          // 104448 B
    const int q_smem  = (128 + 32) * PADU * 4;       // 43520 B
    cudaFuncSetAttribute(kw_kernel, cudaFuncAttributeMaxDynamicSharedMemorySize,
                         kw_smem);
    cudaFuncSetAttribute(q_kernel, cudaFuncAttributeMaxDynamicSharedMemorySize,
                         q_smem);

    conv_item_kernel<<<1184, 256>>>(item_emb);
    eps_kernel<<<(Bb * Ll + 255) / 256, 256>>>();
    kw_kernel<<<KW_GRID, 256, kw_smem>>>(Wk);
    q_kernel<<<Bb / 32, 256, q_smem>>>(user_emb, user_idx, Wq, b_att);
    fused_kernel<<<Bb, 128>>>(user_emb, item_emb, v_att,
                              ln_u_g, ln_u_b, ln_i_g, ln_i_b,
                              pred_W, pred_b, user_hist, user_idx, item_idx, out);
    kl_reduce_kernel<<<1, 256>>>(out, out_size);
}

// round 9
// speedup vs baseline: 1.1584x; 1.0617x over previous
#include <cuda_runtime.h>
#include <cuda_bf16.h>
#include <stdint.h>

#define Dd 128
#define Ll 200
#define Bb 4096
#define NITEMS 100000

// Scratch (static device globals: allocation-free per harness rules)
__device__ __nv_bfloat16 g_KWh[(NITEMS + 1) * Dd];  // item_emb @ Wk (bf16)
__device__ __nv_bfloat16 g_Ih[(NITEMS + 1) * Dd];   // item_emb in bf16 (GEMM input only)
__device__ float g_Q[Bb * Dd];                      // Q = u@Wq + b_att (fp32)
__device__ float g_F1[Bb * Ll];                     // exp(0.1*eps1)
__device__ float g_F2[Bb * Ll];                     // exp(0.1*eps2)
__device__ float g_klp[Bb];
__device__ int   g_cnt[Bb];

// ---------------------------------------------------------------- utilities

__device__ __forceinline__ uint32_t rotl32(uint32_t x, int d) {
    return (x << d) | (x >> (32 - d));
}

// Exact JAX threefry2x32 (20 rounds)
__device__ __forceinline__ void threefry2x32(uint32_t k0, uint32_t k1,
                                             uint32_t c0, uint32_t c1,
                                             uint32_t& o0, uint32_t& o1) {
    uint32_t ks2 = k0 ^ k1 ^ 0x1BD11BDAu;
    uint32_t x0 = c0 + k0, x1 = c1 + k1;
#define TF_R(r) { x0 += x1; x1 = rotl32(x1, r); x1 ^= x0; }
    TF_R(13) TF_R(15) TF_R(26) TF_R(6)  x0 += k1;  x1 += ks2 + 1u;
    TF_R(17) TF_R(29) TF_R(16) TF_R(24) x0 += ks2; x1 += k0 + 2u;
    TF_R(13) TF_R(15) TF_R(26) TF_R(6)  x0 += k0;  x1 += k1 + 3u;
    TF_R(17) TF_R(29) TF_R(16) TF_R(24) x0 += k1;  x1 += ks2 + 4u;
    TF_R(13) TF_R(15) TF_R(26) TF_R(6)  x0 += ks2; x1 += k0 + 5u;
#undef TF_R
    o0 = x0; o1 = x1;
}

// jax.random.normal under jax_threefry_partitionable=True:
//   counter = 64-bit flat index -> (c0 = 0, c1 = idx); 32-bit draw = o0 ^ o1
__device__ __forceinline__ float jax_normal(uint32_t k1, uint32_t idx) {
    uint32_t o0, o1;
    threefry2x32(0u, k1, 0u, idx, o0, o1);
    uint32_t bits = o0 ^ o1;
    float f = __uint_as_float((bits >> 9) | 0x3F800000u) - 1.0f;  // [0,1)
    const float LO = -0.99999994f;                                // nextafter(-1,0)
    float u = fmaf(f, 2.0f, LO);
    u = fmaxf(u, LO);
    return 1.41421356f * erfinvf(u);
}

__device__ __forceinline__ float fast_tanh(float x) {
    float y;
    asm("tanh.approx.f32 %0, %1;" : "=f"(y) : "f"(x));
    return y;
}

__device__ __forceinline__ float breduce_sum(float v, volatile float* red) {
    int tid = threadIdx.x, lane = tid & 31, wrp = tid >> 5;
#pragma unroll
    for (int o = 16; o; o >>= 1) v += __shfl_down_sync(0xffffffffu, v, o);
    if (lane == 0) red[wrp] = v;
    __syncthreads();
    float r = (red[0] + red[1]) + (red[2] + red[3]);
    __syncthreads();
    return r;
}

__device__ __forceinline__ float breduce_max(float v, volatile float* red) {
    int tid = threadIdx.x, lane = tid & 31, wrp = tid >> 5;
#pragma unroll
    for (int o = 16; o; o >>= 1) v = fmaxf(v, __shfl_down_sync(0xffffffffu, v, o));
    if (lane == 0) red[wrp] = v;
    __syncthreads();
    float r = fmaxf(fmaxf(red[0], red[1]), fmaxf(red[2], red[3]));
    __syncthreads();
    return r;
}

// 3-value block sum in one sync round
__device__ __forceinline__ void breduce_sum3(float& a, float& b, float& c,
                                             volatile float* red12) {
    int tid = threadIdx.x, lane = tid & 31, wrp = tid >> 5;
#pragma unroll
    for (int o = 16; o; o >>= 1) {
        a += __shfl_down_sync(0xffffffffu, a, o);
        b += __shfl_down_sync(0xffffffffu, b, o);
        c += __shfl_down_sync(0xffffffffu, c, o);
    }
    if (lane == 0) {
        red12[wrp * 3 + 0] = a;
        red12[wrp * 3 + 1] = b;
        red12[wrp * 3 + 2] = c;
    }
    __syncthreads();
    a = (red12[0] + red12[3]) + (red12[6] + red12[9]);
    b = (red12[1] + red12[4]) + (red12[7] + red12[10]);
    c = (red12[2] + red12[5]) + (red12[8] + red12[11]);
    __syncthreads();
}

// ------------------------------------------- Kernel 0: item_emb -> bf16 table
__global__ __launch_bounds__(256) void conv_item_kernel(const float* __restrict__ item_emb) {
    const int total = (NITEMS + 1) * (Dd / 4);          // float4 count
    for (int i = blockIdx.x * 256 + threadIdx.x; i < total; i += gridDim.x * 256) {
        float4 v = ((const float4*)item_emb)[i];
        __nv_bfloat162 lo = __floats2bfloat162_rn(v.x, v.y);
        __nv_bfloat162 hi = __floats2bfloat162_rn(v.z, v.w);
        uint2 p;
        p.x = *(uint32_t*)&lo;
        p.y = *(uint32_t*)&hi;
        ((uint2*)g_Ih)[i] = p;
    }
}

// ------------------------------------------- Kernel E: precompute lognormal factors
__global__ __launch_bounds__(256) void eps_kernel() {
    int idx = blockIdx.x * 256 + threadIdx.x;
    if (idx < Bb * Ll) {
        float e1 = jax_normal(1u, (uint32_t)idx);
        float e2 = jax_normal(2u, (uint32_t)idx);
        g_F1[idx] = expf(0.1f * e1);
        g_F2[idx] = expf(0.1f * e2);
    }
}

// =================================================================
// bf16 m16n8k16 MMA; smem tiles: uint32 k-pairs, row stride PADU uint32
// =================================================================
#define PADU 68

// ------------------------------------------- Kernel A: KW = item_emb @ Wk (bf16 MMA)
#define KW_GRID 148
#define KW_TILES ((NITEMS + 1 + 127) / 128)   // 782

__global__ __launch_bounds__(256, 2) void kw_kernel(const float* __restrict__ Wk) {
    extern __shared__ uint32_t smem_u[];
    uint32_t* sW  = smem_u;                    // [128 n][68]
    uint32_t* sA0 = smem_u + 128 * PADU;
    uint32_t* sA1 = sA0 + 128 * PADU;

    const int tid  = threadIdx.x;
    const int lane = tid & 31;
    const int wid  = tid >> 5;
    const int gid  = lane >> 2;      // 0..7
    const int tig  = lane & 3;       // 0..3
    const int stripe = (wid & 3) * 32;
    const int colh   = (wid >> 2) * 64;

    // sW[n][p] = {bf16(Wk[2p][n]), bf16(Wk[2p+1][n])}
    // coalesced mapping: n fastest across threads (rows of Wk read as 128B lines)
#pragma unroll 8
    for (int i = tid; i < 64 * 128; i += 256) {
        int p = i >> 7, n = i & 127;
        float a = Wk[(2 * p) * Dd + n];
        float b = Wk[(2 * p + 1) * Dd + n];
        __nv_bfloat162 h = __floats2bfloat162_rn(a, b);
        sW[n * PADU + p] = *(uint32_t*)&h;
    }

    uint32_t* bufs[2] = { sA0, sA1 };
    int cur = 0;
    int t = blockIdx.x;

    // async tile loader: 128 rows x 16 16B-chunks (bf16 rows = 256B)
#define LOAD_TILE(dst, tt) do {                                               \
        const int row0_ = (tt) * 128;                                         \
        for (int i = tid; i < 128 * 16; i += 256) {                           \
            int r_ = i >> 4, c_ = i & 15;                                     \
            int sr_ = row0_ + r_; if (sr_ > NITEMS) sr_ = NITEMS;             \
            const char* src_ = (const char*)g_Ih + (size_t)sr_ * 256 + c_ * 16;\
            uint32_t d_ = (uint32_t)__cvta_generic_to_shared(                 \
                              (dst) + r_ * PADU + c_ * 4);                    \
            asm volatile("cp.async.ca.shared.global [%0], [%1], 16;\n"        \
                         :: "r"(d_), "l"(src_));                              \
        }                                                                     \
    } while (0)

    if (t < KW_TILES) LOAD_TILE(bufs[0], t);
    asm volatile("cp.async.commit_group;\n");

    while (t < KW_TILES) {
        int tn = t + KW_GRID;
        if (tn < KW_TILES) LOAD_TILE(bufs[cur ^ 1], tn);
        asm volatile("cp.async.commit_group;\n");
        asm volatile("cp.async.wait_group 1;\n");
        __syncthreads();

        uint32_t* sA = bufs[cur];
        float acc[2][8][4];
#pragma unroll
        for (int mi = 0; mi < 2; mi++)
#pragma unroll
            for (int ni = 0; ni < 8; ni++)
#pragma unroll
                for (int j = 0; j < 4; j++) acc[mi][ni][j] = 0.f;

#pragma unroll
        for (int ks = 0; ks < 8; ks++) {
            const int p0 = ks * 8;
            uint32_t a[2][4];
#pragma unroll
            for (int mi = 0; mi < 2; mi++) {
                int r = stripe + mi * 16 + gid;
                a[mi][0] = sA[r * PADU + p0 + tig];
                a[mi][1] = sA[(r + 8) * PADU + p0 + tig];
                a[mi][2] = sA[r * PADU + p0 + tig + 4];
                a[mi][3] = sA[(r + 8) * PADU + p0 + tig + 4];
            }
            uint32_t bf[8][2];
#pragma unroll
            for (int ni = 0; ni < 8; ni++) {
                int n = colh + ni * 8 + gid;
                bf[ni][0] = sW[n * PADU + p0 + tig];
                bf[ni][1] = sW[n * PADU + p0 + tig + 4];
            }
#pragma unroll
            for (int mi = 0; mi < 2; mi++)
#pragma unroll
                for (int ni = 0; ni < 8; ni++) {
                    asm volatile(
                        "mma.sync.aligned.m16n8k16.row.col.f32.bf16.bf16.f32 "
                        "{%0,%1,%2,%3}, {%4,%5,%6,%7}, {%8,%9}, {%0,%1,%2,%3};"
                        : "+f"(acc[mi][ni][0]), "+f"(acc[mi][ni][1]),
                          "+f"(acc[mi][ni][2]), "+f"(acc[mi][ni][3])
                        : "r"(a[mi][0]), "r"(a[mi][1]), "r"(a[mi][2]), "r"(a[mi][3]),
                          "r"(bf[ni][0]), "r"(bf[ni][1]));
                }
        }

        // epilogue: bf16 pack + store
        const int row0 = t * 128;
        uint32_t* kw32 = (uint32_t*)g_KWh;
#pragma unroll
        for (int mi = 0; mi < 2; mi++) {
            int r0 = row0 + stripe + mi * 16 + gid;
            int r1 = r0 + 8;
#pragma unroll
            for (int ni = 0; ni < 8; ni++) {
                int c = colh + ni * 8 + tig * 2;
                if (r0 <= NITEMS) {
                    __nv_bfloat162 h = __floats2bfloat162_rn(acc[mi][ni][0], acc[mi][ni][1]);
                    kw32[(size_t)r0 * (Dd / 2) + (c >> 1)] = *(uint32_t*)&h;
                }
                if (r1 <= NITEMS) {
                    __nv_bfloat162 h = __floats2bfloat162_rn(acc[mi][ni][2], acc[mi][ni][3]);
                    kw32[(size_t)r1 * (Dd / 2) + (c >> 1)] = *(uint32_t*)&h;
                }
            }
        }
        __syncthreads();
        cur ^= 1;
        t = tn;
    }
#undef LOAD_TILE
}

// ------------------------------------------- Kernel B: Q = user_emb[uidx] @ Wq + b_att
// 128 blocks x 256 thr; 32-row tiles; user gather + bf16 convert fused in.
__global__ __launch_bounds__(256) void q_kernel(const float* __restrict__ user_emb,
                                                const int* __restrict__ user_idx,
                                                const float* __restrict__ Wq,
                                                const float* __restrict__ b_att) {
    extern __shared__ uint32_t smem_u[];
    uint32_t* sW = smem_u;                 // [128 n][68]
    uint32_t* sA = smem_u + 128 * PADU;    // [32 m][68]

    const int tid  = threadIdx.x;
    const int lane = tid & 31;
    const int wid  = tid >> 5;
    const int gid  = lane >> 2;
    const int tig  = lane & 3;
    const int mrow = (wid & 1) * 16;
    const int ncol = (wid >> 1) * 32;
    const int row0 = blockIdx.x * 32;

    // coalesced Wq fill (n fastest across threads)
#pragma unroll 8
    for (int i = tid; i < 64 * 128; i += 256) {
        int p = i >> 7, n = i & 127;
        float a = Wq[(2 * p) * Dd + n];
        float b = Wq[(2 * p + 1) * Dd + n];
        __nv_bfloat162 h = __floats2bfloat162_rn(a, b);
        sW[n * PADU + p] = *(uint32_t*)&h;
    }
#pragma unroll
    for (int i = tid; i < 32 * 64; i += 256) {
        int r = i >> 6, p = i & 63;
        int u = user_idx[row0 + r];
        float2 v = *(const float2*)(user_emb + (size_t)u * Dd + 2 * p);
        __nv_bfloat162 h = __floats2bfloat162_rn(v.x, v.y);
        sA[r * PADU + p] = *(uint32_t*)&h;
    }
    __syncthreads();

    float acc[4][4];
#pragma unroll
    for (int ni = 0; ni < 4; ni++)
#pragma unroll
        for (int j = 0; j < 4; j++) acc[ni][j] = 0.f;

#pragma unroll
    for (int ks = 0; ks < 8; ks++) {
        const int p0 = ks * 8;
        uint32_t a[4];
        a[0] = sA[(mrow + gid) * PADU + p0 + tig];
        a[1] = sA[(mrow + 8 + gid) * PADU + p0 + tig];
        a[2] = sA[(mrow + gid) * PADU + p0 + tig + 4];
        a[3] = sA[(mrow + 8 + gid) * PADU + p0 + tig + 4];
        uint32_t bf[4][2];
#pragma unroll
        for (int ni = 0; ni < 4; ni++) {
            int n = ncol + ni * 8 + gid;
            bf[ni][0] = sW[n * PADU + p0 + tig];
            bf[ni][1] = sW[n * PADU + p0 + tig + 4];
        }
#pragma unroll
        for (int ni = 0; ni < 4; ni++) {
            asm volatile(
                "mma.sync.aligned.m16n8k16.row.col.f32.bf16.bf16.f32 "
                "{%0,%1,%2,%3}, {%4,%5,%6,%7}, {%8,%9}, {%0,%1,%2,%3};"
                : "+f"(acc[ni][0]), "+f"(acc[ni][1]),
                  "+f"(acc[ni][2]), "+f"(acc[ni][3])
                : "r"(a[0]), "r"(a[1]), "r"(a[2]), "r"(a[3]),
                  "r"(bf[ni][0]), "r"(bf[ni][1]));
        }
    }

    {
        int r0 = row0 + mrow + gid;
        int r1 = r0 + 8;
#pragma unroll
        for (int ni = 0; ni < 4; ni++) {
            int c = ncol + ni * 8 + tig * 2;
            float2 ba = *(const float2*)(b_att + c);
            *(float2*)(g_Q + (size_t)r0 * Dd + c) =
                make_float2(acc[ni][0] + ba.x, acc[ni][1] + ba.y);
            *(float2*)(g_Q + (size_t)r1 * Dd + c) =
                make_float2(acc[ni][2] + ba.x, acc[ni][3] + ba.y);
        }
    }
}

// ------------------------------------------- Kernel C: fused BAM forward
__global__ __launch_bounds__(128, 8) void fused_kernel(
    const float* __restrict__ user_emb,
    const float* __restrict__ item_emb,
    const float* __restrict__ v_att,
    const float* __restrict__ ln_u_g, const float* __restrict__ ln_u_b,
    const float* __restrict__ ln_i_g, const float* __restrict__ ln_i_b,
    const float* __restrict__ pred_W, const float* __restrict__ pred_b,
    const int* __restrict__ user_hist,
    const int* __restrict__ user_idx,
    const int* __restrict__ item_idx,
    float* __restrict__ out)
{
    __shared__ __align__(16) float sh_q[Dd];
    __shared__ __align__(16) float sh_u[Dd];
    __shared__ __align__(16) float sh_v[Dd];
    __shared__ int   sh_r[Ll];
    __shared__ float sh_s[Ll];
    __shared__ float sh_w1[Ll];
    __shared__ float sh_w2[Ll];
    __shared__ float red[12];

    const int tid  = threadIdx.x;
    const int lane = tid & 31;
    const int wrp  = tid >> 5;
    const int b    = blockIdx.x;
    const int uidx = user_idx[b];
    const int tgt  = item_idx[b];

    sh_u[tid] = user_emb[(size_t)uidx * Dd + tid];
    sh_q[tid] = g_Q[(size_t)b * Dd + tid];     // includes b_att
    sh_v[tid] = v_att[tid];
    float validf = 0.f;
    for (int l = tid; l < Ll; l += 128) {
        int r = user_hist[(size_t)uidx * Ll + l];
        bool ok = (r != tgt) && (r != NITEMS);
        sh_r[l] = ok ? r : -1;
        validf += ok ? 1.f : 0.f;
    }
    __syncthreads();

    float nvf = breduce_sum(validf, red);
    int n_valid = (int)(nvf + 0.5f);
    float nv_clamped = (n_valid > 0) ? (float)n_valid : 1.0f;
    float mu_p = -logf(nv_clamped);

    // scores: warp per l, 2 rows per iteration; lane covers 4 dims (8B bf16)
    float4 q4, v4;
    {
        float2 qa = *(const float2*)(sh_q + lane * 4);
        float2 qb = *(const float2*)(sh_q + lane * 4 + 2);
        q4 = make_float4(qa.x, qa.y, qb.x, qb.y);
        float2 va = *(const float2*)(sh_v + lane * 4);
        float2 vb = *(const float2*)(sh_v + lane * 4 + 2);
        v4 = make_float4(va.x, va.y, vb.x, vb.y);
    }
    for (int l = wrp; l < Ll; l += 8) {
        int l1 = l + 4;
        int r0 = sh_r[l];
        int r1 = (l1 < Ll) ? sh_r[l1] : -1;
        uint2 raw0 = make_uint2(0u, 0u), raw1 = make_uint2(0u, 0u);
        if (r0 >= 0)
            raw0 = ((const uint2*)(g_KWh + (size_t)r0 * Dd))[lane];
        if (r1 >= 0)
            raw1 = ((const uint2*)(g_KWh + (size_t)r1 * Dd))[lane];

#pragma unroll
        for (int j = 0; j < 2; j++) {
            int rr = j ? r1 : r0;
            int ll = j ? l1 : l;
            if (ll >= Ll) break;
            float sval = -1e30f;
            if (rr >= 0) {
                uint2 raw = j ? raw1 : raw0;
                float2 f0 = __bfloat1622float2(*(__nv_bfloat162*)&raw.x);
                float2 f1 = __bfloat1622float2(*(__nv_bfloat162*)&raw.y);
                float tv = v4.x * fast_tanh(q4.x + f0.x);
                tv = fmaf(v4.y, fast_tanh(q4.y + f0.y), tv);
                tv = fmaf(v4.z, fast_tanh(q4.z + f1.x), tv);
                tv = fmaf(v4.w, fast_tanh(q4.w + f1.y), tv);
#pragma unroll
                for (int o = 16; o; o >>= 1)
                    tv += __shfl_down_sync(0xffffffffu, tv, o);
                sval = tv * 0.25f;   // / TAU
            }
            if (lane == 0) sh_s[ll] = sval;
        }
    }
    __syncthreads();

    // softmax
    float m = -1e30f;
    for (int l = tid; l < Ll; l += 128) m = fmaxf(m, sh_s[l]);
    m = breduce_max(m, red);

    float esum = 0.f;
    for (int l = tid; l < Ll; l += 128) {
        float e = 0.f;
        if (sh_r[l] >= 0) e = expf(sh_s[l] - m);
        sh_s[l] = e;
        esum += e;
    }
    esum = breduce_sum(esum, red);
    float inv_es = (esum > 0.f) ? (1.0f / esum) : 0.f;

    // sampled weights via precomputed lognormal factors + KL; triple reduce
    float klacc = 0.f, s1 = 0.f, s2 = 0.f;
    for (int l = tid; l < Ll; l += 128) {
        float w1 = 0.f, w2 = 0.f;
        if (sh_r[l] >= 0) {
            float alpha = sh_s[l] * inv_es;
            float ap = alpha + 1e-24f;
            float mu = logf(ap);
            int idx = b * Ll + l;
            w1 = ap * g_F1[idx];
            w2 = ap * g_F2[idx];
            float dmu = mu - mu_p;
            klacc += 1.8075851f + 0.5f * dmu * dmu;  // log(10)-0.5+SIG_Q^2/2 + d^2/2
        }
        sh_w1[l] = w1;
        sh_w2[l] = w2;
        s1 += w1;
        s2 += w2;
    }
    breduce_sum3(klacc, s1, s2, red);
    if (tid == 0) { g_klp[b] = klacc; g_cnt[b] = n_valid; }
    float i1 = 1.0f / (s1 + 1e-12f);
    float i2 = 1.0f / (s2 + 1e-12f);

    // contexts: fp32 item_emb gather (value path stays fp32),
    // 4 batched loads per group; one gather serves both draws
    float cu = 0.f, ci = 0.f;
    for (int l0 = 0; l0 < Ll; l0 += 4) {
        float vv[4];
#pragma unroll
        for (int j = 0; j < 4; j++) {
            int r = sh_r[l0 + j];
            vv[j] = (r >= 0) ? item_emb[(size_t)r * Dd + tid] : 0.f;
        }
#pragma unroll
        for (int j = 0; j < 4; j++) {
            cu = fmaf(sh_w1[l0 + j], vv[j], cu);
            ci = fmaf(sh_w2[l0 + j], vv[j], ci);
        }
    }
    cu *= i1; ci *= i2;

    // layernorm(u ctx * user_emb)
    float xu = cu * sh_u[tid];
    float mean_u = breduce_sum(xu, red) * (1.0f / Dd);
    float du = xu - mean_u;
    float var_u = breduce_sum(du * du, red) * (1.0f / Dd);
    float us = du * rsqrtf(var_u + 1e-5f) * ln_u_g[tid] + ln_u_b[tid];

    // layernorm(i ctx * item_emb[target])
    float xi = ci * item_emb[(size_t)tgt * Dd + tid];
    float mean_i = breduce_sum(xi, red) * (1.0f / Dd);
    float di = xi - mean_i;
    float var_i = breduce_sum(di * di, red) * (1.0f / Dd);
    float is_ = di * rsqrtf(var_i + 1e-5f) * ln_i_g[tid] + ln_i_b[tid];

    float pv = us * is_ * pred_W[tid];
    float dot = breduce_sum(pv, red);
    if (tid == 0) out[b] = dot + pred_b[0];
}

// ------------------------------------------- Kernel D: deterministic KL reduce
__global__ __launch_bounds__(256) void kl_reduce_kernel(float* __restrict__ out,
                                                        int out_size) {
    __shared__ float rs[8];
    __shared__ int   ri[8];
    int tid = threadIdx.x;
    float s = 0.f; int c = 0;
    for (int i = tid; i < Bb; i += 256) { s += g_klp[i]; c += g_cnt[i]; }
#pragma unroll
    for (int o = 16; o; o >>= 1) {
        s += __shfl_down_sync(0xffffffffu, s, o);
        c += __shfl_down_sync(0xffffffffu, c, o);
    }
    if ((tid & 31) == 0) { rs[tid >> 5] = s; ri[tid >> 5] = c; }
    __syncthreads();
    if (tid == 0) {
        float S = 0.f; int C = 0;
        for (int i = 0; i < 8; i++) { S += rs[i]; C += ri[i]; }
        if (C < 1) C = 1;
        float kl = 0.25f * S / (float)C;   // BETA * sum / cnt ; (kl_u+kl_i)/2 == kl_u
        if (out_size > Bb) out[Bb] = kl;
    }
}

// ------------------------------------------- launcher
extern "C" void kernel_launch(void* const* d_in, const int* in_sizes, int n_in,
                              void* d_out, int out_size) {
    const float* user_emb = (const float*)d_in[0];
    const float* item_emb = (const float*)d_in[1];
    const float* Wq       = (const float*)d_in[2];
    const float* Wk       = (const float*)d_in[3];
    const float* b_att    = (const float*)d_in[4];
    const float* v_att    = (const float*)d_in[5];
    const float* ln_u_g   = (const float*)d_in[6];
    const float* ln_u_b   = (const float*)d_in[7];
    const float* ln_i_g   = (const float*)d_in[8];
    const float* ln_i_b   = (const float*)d_in[9];
    const float* pred_W   = (const float*)d_in[10];
    const float* pred_b   = (const float*)d_in[11];
    const int* user_hist  = (const int*)d_in[12];
    const int* user_idx   = (const int*)d_in[13];
    const int* item_idx   = (const int*)d_in[14];
    float* out = (float*)d_out;

    // side streams/events (created once, outside any capture; host-side
    // resources only — no device memory)
    static cudaStream_t s1 = nullptr, s2 = nullptr;
    static cudaEvent_t evRoot = nullptr, ev1 = nullptr, ev2 = nullptr;
    if (s1 == nullptr) {
        cudaStreamCreateWithFlags(&s1, cudaStreamNonBlocking);
        cudaStreamCreateWithFlags(&s2, cudaStreamNonBlocking);
        cudaEventCreateWithFlags(&evRoot, cudaEventDisableTiming);
        cudaEventCreateWithFlags(&ev1, cudaEventDisableTiming);
        cudaEventCreateWithFlags(&ev2, cudaEventDisableTiming);
    }

    const int kw_smem = 3 * 128 * PADU * 4;          // 104448 B
    const int q_smem  = (128 + 32) * PADU * 4;       // 43520 B
    cudaFuncSetAttribute(kw_kernel, cudaFuncAttributeMaxDynamicSharedMemorySize,
                         kw_smem);
    cudaFuncSetAttribute(q_kernel, cudaFuncAttributeMaxDynamicSharedMemorySize,
                         q_smem);

    // fork: eps on s1, q on s2, conv+kw on main stream
    cudaEventRecord(evRoot, 0);
    cudaStreamWaitEvent(s1, evRoot, 0);
    cudaStreamWaitEvent(s2, evRoot, 0);

    eps_kernel<<<(Bb * Ll + 255) / 256, 256, 0, s1>>>();
    q_kernel<<<Bb / 32, 256, q_smem, s2>>>(user_emb, user_idx, Wq, b_att);

    conv_item_kernel<<<1184, 256>>>(item_emb);
    kw_kernel<<<KW_GRID, 256, kw_smem>>>(Wk);

    // join
    cudaEventRecord(ev1, s1);
    cudaEventRecord(ev2, s2);
    cudaStreamWaitEvent(0, ev1, 0);
    cudaStreamWaitEvent(0, ev2, 0);

    fused_kernel<<<Bb, 128>>>(user_emb, item_emb, v_att,
                              ln_u_g, ln_u_b, ln_i_g, ln_i_b,
                              pred_W, pred_b, user_hist, user_idx, item_idx, out);
    kl_reduce_kernel<<<1, 256>>>(out, out_size);
}